// round 1
// baseline (speedup 1.0000x reference)
#include <cuda_runtime.h>

// Problem constants (fixed shapes from setup_inputs)
#define NTOK   16384        // H*W = 128*128
#define MROWS  131072       // B * NTOK
#define EDIM   256

// Scratch: xp = x@W_in (token-major, 256ch), y = attention output (token-major, 256ch)
__device__ float g_xp[33554432];
__device__ float g_y[33554432];

// ---------------------------------------------------------------------------
// SGEMM: C[M x 256] = A[M x 256] @ W[256 x 256] + bias, fp32.
// 128x128 block tile, k-tile 16, 256 threads, 8x8 register microtile.
// ---------------------------------------------------------------------------
__global__ __launch_bounds__(256, 2) void sgemm256(const float* __restrict__ A,
                                                   const float* __restrict__ Bw,
                                                   const float* __restrict__ bias,
                                                   float* __restrict__ C)
{
    __shared__ float As[16][128];
    __shared__ float Bs[16][128];
    const int t    = threadIdx.x;
    const int row0 = blockIdx.y << 7;
    const int col0 = blockIdx.x << 7;
    const int tx   = t & 15;   // n microtile group
    const int ty   = t >> 4;   // m microtile group

    float acc[8][8];
#pragma unroll
    for (int i = 0; i < 8; i++)
#pragma unroll
        for (int j = 0; j < 8; j++) acc[i][j] = 0.f;

    for (int k0 = 0; k0 < 256; k0 += 16) {
        // Load A tile 128x16 (transpose into As[k][m])
#pragma unroll
        for (int i = 0; i < 2; i++) {
            const int v  = (t << 1) | i;        // float4 index [0,512)
            const int ar = v >> 2;              // row in tile
            const int kq = (v & 3) << 2;        // k offset
            const float4 a4 = *(const float4*)(A + (size_t)(row0 + ar) * 256 + k0 + kq);
            As[kq + 0][ar] = a4.x;
            As[kq + 1][ar] = a4.y;
            As[kq + 2][ar] = a4.z;
            As[kq + 3][ar] = a4.w;
        }
        // Load B tile 16x128 (direct)
#pragma unroll
        for (int i = 0; i < 2; i++) {
            const int v  = (t << 1) | i;
            const int kr = v >> 5;
            const int nq = (v & 31) << 2;
            *(float4*)&Bs[kr][nq] =
                *(const float4*)(Bw + (size_t)(k0 + kr) * 256 + col0 + nq);
        }
        __syncthreads();

#pragma unroll
        for (int kk = 0; kk < 16; kk++) {
            float a[8], b[8];
            *(float4*)&a[0] = *(float4*)&As[kk][ty * 8];
            *(float4*)&a[4] = *(float4*)&As[kk][ty * 8 + 4];
            *(float4*)&b[0] = *(float4*)&Bs[kk][tx * 8];
            *(float4*)&b[4] = *(float4*)&Bs[kk][tx * 8 + 4];
#pragma unroll
            for (int i = 0; i < 8; i++)
#pragma unroll
                for (int j = 0; j < 8; j++)
                    acc[i][j] = fmaf(a[i], b[j], acc[i][j]);
        }
        __syncthreads();
    }

    // Epilogue: + bias, store
#pragma unroll
    for (int i = 0; i < 8; i++) {
        const int r = row0 + ty * 8 + i;
#pragma unroll
        for (int j = 0; j < 8; j += 4) {
            const int c = col0 + tx * 8 + j;
            float4 o;
            o.x = acc[i][j + 0] + bias[c + 0];
            o.y = acc[i][j + 1] + bias[c + 1];
            o.z = acc[i][j + 2] + bias[c + 2];
            o.w = acc[i][j + 3] + bias[c + 3];
            *(float4*)(C + (size_t)r * 256 + c) = o;
        }
    }
}

// ---------------------------------------------------------------------------
// Attention: per (head h, batch b, block blk):
//   xb[0:64]  = xp[local 8x8 tokens of blk][h*32 : h*32+32]
//   xb[64:80] = weights[b,blk,j] * xp[indexes[b,blk,j]][h slice]
//   out = A(64x80) @ xb(80x32); scatter to g_y token-major.
// 128 threads; each computes 4q x 4d register tile.
// ---------------------------------------------------------------------------
__global__ __launch_bounds__(128) void attn_kernel(const float* __restrict__ aw,
                                                   const int*   __restrict__ idx,
                                                   const float* __restrict__ wsel)
{
    __shared__ float sA[64][81];   // padded: stride 81 kills q-stride conflicts
    __shared__ float sX[80][32];

    const int t   = threadIdx.x;
    const int bid = blockIdx.x;            // = (h*8 + b)*256 + blk
    const int blk = bid & 255;
    const int b   = (bid >> 8) & 7;
    const int h   = bid >> 11;
    const int bh  = blk >> 4;
    const int bw  = blk & 15;

    // Load attention matrix A: 64x80 floats = 1280 float4, 10 per thread
    const float* Ab = aw + (size_t)bid * 5120;
#pragma unroll
    for (int i = 0; i < 10; i++) {
        const int v  = i * 128 + t;        // [0,1280)
        const int q  = v / 20;
        const int kq = (v % 20) << 2;
        const float4 a4 = *(const float4*)(Ab + q * 80 + kq);
        sA[q][kq + 0] = a4.x;
        sA[q][kq + 1] = a4.y;
        sA[q][kq + 2] = a4.z;
        sA[q][kq + 3] = a4.w;
    }

    const size_t xbase = (size_t)b * NTOK * 256 + h * 32;

    // Local tokens: 64 tokens x 32 ch = 512 float4, 4 per thread
#pragma unroll
    for (int i = 0; i < 4; i++) {
        const int v  = i * 128 + t;        // [0,512)
        const int p  = v >> 3;             // token-in-block 0..63
        const int dq = (v & 7) << 2;       // channel offset 0..28
        const int r  = p >> 3, c = p & 7;
        const int sp = (bh * 8 + r) * 128 + bw * 8 + c;
        *(float4*)&sX[p][dq] =
            *(const float4*)(g_xp + xbase + (size_t)sp * 256 + dq);
    }

    // Selected tokens: 16 tokens x 32 ch = 128 float4, 1 per thread
    {
        const int j    = t >> 3;
        const int dq   = (t & 7) << 2;
        const int base = (b * 256 + blk) * 16 + j;
        const int tok  = idx[base];
        const float w  = wsel[base];
        const float4 v4 = *(const float4*)(g_xp + xbase + (size_t)tok * 256 + dq);
        sX[64 + j][dq + 0] = v4.x * w;
        sX[64 + j][dq + 1] = v4.y * w;
        sX[64 + j][dq + 2] = v4.z * w;
        sX[64 + j][dq + 3] = v4.w * w;
    }
    __syncthreads();

    const int qg = t >> 3;   // 0..15 -> rows qg*4..+3
    const int dg = t & 7;    // 0..7  -> cols dg*4..+3
    float acc[4][4];
#pragma unroll
    for (int i = 0; i < 4; i++)
#pragma unroll
        for (int j = 0; j < 4; j++) acc[i][j] = 0.f;

#pragma unroll 4
    for (int k = 0; k < 80; k++) {
        const float4 x4 = *(const float4*)&sX[k][dg << 2];
        const float xv[4] = {x4.x, x4.y, x4.z, x4.w};
#pragma unroll
        for (int i = 0; i < 4; i++) {
            const float a = sA[qg * 4 + i][k];
#pragma unroll
            for (int j = 0; j < 4; j++)
                acc[i][j] = fmaf(a, xv[j], acc[i][j]);
        }
    }

    // Scatter to token-major y
#pragma unroll
    for (int i = 0; i < 4; i++) {
        const int q  = qg * 4 + i;
        const int r  = q >> 3, c = q & 7;
        const int sp = (bh * 8 + r) * 128 + bw * 8 + c;
        const float4 o = make_float4(acc[i][0], acc[i][1], acc[i][2], acc[i][3]);
        *(float4*)(g_y + xbase + (size_t)sp * 256 + (dg << 2)) = o;
    }
}

// ---------------------------------------------------------------------------
extern "C" void kernel_launch(void* const* d_in, const int* in_sizes, int n_in,
                              void* d_out, int out_size)
{
    const float* x    = (const float*)d_in[0];
    const float* aw   = (const float*)d_in[1];
    const int*   idx  = (const int*)d_in[2];
    const float* wsel = (const float*)d_in[3];
    const float* Win  = (const float*)d_in[4];
    const float* bin  = (const float*)d_in[5];
    const float* Wout = (const float*)d_in[6];
    const float* bout = (const float*)d_in[7];
    float* out = (float*)d_out;

    float *xp_ptr, *y_ptr;
    cudaGetSymbolAddress((void**)&xp_ptr, g_xp);
    cudaGetSymbolAddress((void**)&y_ptr, g_y);

    // Stage 1: xp = x @ W_in + b_in
    sgemm256<<<dim3(2, 1024), 256>>>(x, Win, bin, xp_ptr);
    // Stage 2: block attention with top-k gather
    attn_kernel<<<16384, 128>>>(aw, idx, wsel);
    // Stage 3: out = y @ W_out + b_out
    sgemm256<<<dim3(2, 1024), 256>>>(y_ptr, Wout, bout, out);
}

// round 3
// speedup vs baseline: 1.7004x; 1.7004x over previous
#include <cuda_runtime.h>
#include <cuda_bf16.h>
#include <cstdint>

#define NTOK 16384

// Scratch (allocation-free rule: __device__ globals)
__device__ float g_xp[33554432];             // x @ W_in
__device__ float g_y[33554432];              // attention output
__device__ __nv_bfloat16 g_wth1[65536];      // W_in^T  hi (bf16, [n][k])
__device__ __nv_bfloat16 g_wtl1[65536];      // W_in^T  lo
__device__ __nv_bfloat16 g_wth2[65536];      // W_out^T hi
__device__ __nv_bfloat16 g_wtl2[65536];      // W_out^T lo

// ---------------------------------------------------------------------------
__device__ __forceinline__ uint32_t smem_u32(const void* p) {
    uint32_t a;
    asm("{ .reg .u64 t; cvta.to.shared.u64 t, %1; cvt.u32.u64 %0, t; }"
        : "=r"(a) : "l"(p));
    return a;
}

#define LDSM4(R0, R1, R2, R3, addr) \
    asm volatile("ldmatrix.sync.aligned.m8n8.x4.shared.b16 {%0,%1,%2,%3}, [%4];" \
                 : "=r"(R0), "=r"(R1), "=r"(R2), "=r"(R3) : "r"(addr))

__device__ __forceinline__ void mma16816(float* d, const uint32_t* a,
                                         const uint32_t* b) {
    asm volatile(
        "mma.sync.aligned.m16n8k16.row.col.f32.bf16.bf16.f32 "
        "{%0,%1,%2,%3}, {%4,%5,%6,%7}, {%8,%9}, {%0,%1,%2,%3};"
        : "+f"(d[0]), "+f"(d[1]), "+f"(d[2]), "+f"(d[3])
        : "r"(a[0]), "r"(a[1]), "r"(a[2]), "r"(a[3]), "r"(b[0]), "r"(b[1]));
}

// Split two floats into packed-bf16 hi and lo words
__device__ __forceinline__ void split2(float x, float y, uint32_t& hi, uint32_t& lo) {
    __nv_bfloat16 hx = __float2bfloat16_rn(x);
    __nv_bfloat16 hy = __float2bfloat16_rn(y);
    float lx = x - __bfloat162float(hx);
    float ly = y - __bfloat162float(hy);
    __nv_bfloat16 lxb = __float2bfloat16_rn(lx);
    __nv_bfloat16 lyb = __float2bfloat16_rn(ly);
    __nv_bfloat162 hp = __halves2bfloat162(hx, hy);
    __nv_bfloat162 lp = __halves2bfloat162(lxb, lyb);
    hi = *(uint32_t*)&hp;
    lo = *(uint32_t*)&lp;
}

// ---------------------------------------------------------------------------
// Transpose + bf16 hi/lo split: Th/Tl[n][k] = split(W[k][n]), 256x256
// ---------------------------------------------------------------------------
__global__ void transpose_split(const float* __restrict__ W,
                                __nv_bfloat16* __restrict__ Th,
                                __nv_bfloat16* __restrict__ Tl)
{
    __shared__ float tile[32][33];
    const int bx = (blockIdx.x & 7) << 5;    // n-range
    const int by = (blockIdx.x >> 3) << 5;   // k-range
    const int tx = threadIdx.x & 31;
    const int ty = threadIdx.x >> 5;
#pragma unroll
    for (int i = 0; i < 32; i += 8)
        tile[ty + i][tx] = W[(by + ty + i) * 256 + bx + tx];
    __syncthreads();
#pragma unroll
    for (int i = 0; i < 32; i += 8) {
        const float v = tile[tx][ty + i];
        const __nv_bfloat16 h = __float2bfloat16_rn(v);
        const float l = v - __bfloat162float(h);
        Th[(bx + ty + i) * 256 + by + tx] = h;
        Tl[(bx + ty + i) * 256 + by + tx] = __float2bfloat16_rn(l);
    }
}

// ---------------------------------------------------------------------------
// 3xBF16 warp-MMA GEMM: C[M x 256] = A[M x 256] @ Bt^T + bias
//   Bt pre-split bf16 hi/lo, [N=256][K=256] K-major.
//   CTA: 128x128 tile, BK=32, 256 threads, 8 warps (2M x 4N), warp 64x32.
// ---------------------------------------------------------------------------
#define SROW 80                    // bytes per smem row (32 bf16 + 8 pad)
#define OFF_AH 0
#define OFF_AL 10240
#define OFF_BH 20480
#define OFF_BL 30720
#define BUFB   40960
#define GEMM_SMEM (2 * BUFB)

__global__ __launch_bounds__(256) void gemm_bf16x3(const float* __restrict__ A,
                                                   const __nv_bfloat16* __restrict__ Bh,
                                                   const __nv_bfloat16* __restrict__ Bl,
                                                   const float* __restrict__ bias,
                                                   float* __restrict__ C)
{
    extern __shared__ char sm[];
    const uint32_t smb = smem_u32(sm);
    const int t    = threadIdx.x;
    const int lane = t & 31;
    const int warp = t >> 5;
    const int wm0  = (warp >> 2) * 64;   // warp M offset in tile
    const int wn0  = (warp & 3) * 32;    // warp N offset in tile
    const int row0 = blockIdx.y << 7;
    const int col0 = blockIdx.x << 7;

    // per-thread global load mapping: r = i*32 + (t>>3), k4 = (t&7)*4
    const int lr = t >> 3;
    const int lk = (t & 7) << 2;

    float acc[4][4][4];
#pragma unroll
    for (int i = 0; i < 4; i++)
#pragma unroll
        for (int j = 0; j < 4; j++)
#pragma unroll
            for (int k = 0; k < 4; k++) acc[i][j][k] = 0.f;

    float4 pa[4];
    uint2  pbh[4], pbl[4];

    // ldmatrix per-thread base offsets (bytes)
    const uint32_t aoff = (uint32_t)(wm0 + (lane & 15)) * SROW + ((lane >> 4) << 4);
    const uint32_t boff = (uint32_t)(wn0 + (lane & 15)) * SROW + ((lane >> 4) << 4);

#define LOAD_CHUNK(k0)                                                          \
    do {                                                                        \
        _Pragma("unroll")                                                       \
        for (int i = 0; i < 4; i++) {                                           \
            const int r = i * 32 + lr;                                          \
            pa[i]  = *(const float4*)(A  + (size_t)(row0 + r) * 256 + (k0) + lk); \
            pbh[i] = *(const uint2*)(Bh + (size_t)(col0 + r) * 256 + (k0) + lk); \
            pbl[i] = *(const uint2*)(Bl + (size_t)(col0 + r) * 256 + (k0) + lk); \
        }                                                                       \
    } while (0)

#define STORE_CHUNK(bufoff)                                                     \
    do {                                                                        \
        char* base = sm + (bufoff);                                             \
        _Pragma("unroll")                                                       \
        for (int i = 0; i < 4; i++) {                                           \
            const int r = i * 32 + lr;                                          \
            const uint32_t off = (uint32_t)r * SROW + ((t & 7) << 3);           \
            uint2 h, l;                                                         \
            split2(pa[i].x, pa[i].y, h.x, l.x);                                 \
            split2(pa[i].z, pa[i].w, h.y, l.y);                                 \
            *(uint2*)(base + OFF_AH + off) = h;                                 \
            *(uint2*)(base + OFF_AL + off) = l;                                 \
            *(uint2*)(base + OFF_BH + off) = pbh[i];                            \
            *(uint2*)(base + OFF_BL + off) = pbl[i];                            \
        }                                                                       \
    } while (0)

    LOAD_CHUNK(0);
    STORE_CHUNK(0);
    __syncthreads();

    for (int c = 0; c < 8; c++) {
        const uint32_t cur = (uint32_t)(c & 1) * BUFB;
        const uint32_t nxt = BUFB - cur;
        if (c < 7) LOAD_CHUNK((c + 1) * 32);

        const uint32_t AH = smb + cur + OFF_AH;
        const uint32_t AL = smb + cur + OFF_AL;
        const uint32_t BH = smb + cur + OFF_BH;
        const uint32_t BL = smb + cur + OFF_BL;

#pragma unroll
        for (int ks = 0; ks < 2; ks++) {
            const uint32_t kb = ks * 32;   // bytes
            uint32_t ah[4][4], al[4][4], bf[4][2];
#pragma unroll
            for (int mf = 0; mf < 4; mf++)
                LDSM4(ah[mf][0], ah[mf][1], ah[mf][2], ah[mf][3],
                      AH + aoff + mf * (16 * SROW) + kb);
#pragma unroll
            for (int mf = 0; mf < 4; mf++)
                LDSM4(al[mf][0], al[mf][1], al[mf][2], al[mf][3],
                      AL + aoff + mf * (16 * SROW) + kb);
            // B hi
#pragma unroll
            for (int np = 0; np < 2; np++) {
                uint32_t r0, r1, r2, r3;
                LDSM4(r0, r1, r2, r3, BH + boff + np * (16 * SROW) + kb);
                bf[2 * np][0] = r0; bf[2 * np][1] = r2;
                bf[2 * np + 1][0] = r1; bf[2 * np + 1][1] = r3;
            }
#pragma unroll
            for (int mf = 0; mf < 4; mf++)
#pragma unroll
                for (int nf = 0; nf < 4; nf++)
                    mma16816(acc[mf][nf], ah[mf], bf[nf]);
#pragma unroll
            for (int mf = 0; mf < 4; mf++)
#pragma unroll
                for (int nf = 0; nf < 4; nf++)
                    mma16816(acc[mf][nf], al[mf], bf[nf]);
            // B lo (reuse bf regs)
#pragma unroll
            for (int np = 0; np < 2; np++) {
                uint32_t r0, r1, r2, r3;
                LDSM4(r0, r1, r2, r3, BL + boff + np * (16 * SROW) + kb);
                bf[2 * np][0] = r0; bf[2 * np][1] = r2;
                bf[2 * np + 1][0] = r1; bf[2 * np + 1][1] = r3;
            }
#pragma unroll
            for (int mf = 0; mf < 4; mf++)
#pragma unroll
                for (int nf = 0; nf < 4; nf++)
                    mma16816(acc[mf][nf], ah[mf], bf[nf]);
        }

        if (c < 7) STORE_CHUNK(nxt);
        __syncthreads();
    }

    // Epilogue: direct stores, +bias
#pragma unroll
    for (int nf = 0; nf < 4; nf++) {
        const int cc = col0 + wn0 + nf * 8 + (lane & 3) * 2;
        const float b0 = bias[cc], b1 = bias[cc + 1];
#pragma unroll
        for (int mf = 0; mf < 4; mf++) {
            const int r = row0 + wm0 + mf * 16 + (lane >> 2);
            float2 o0 = make_float2(acc[mf][nf][0] + b0, acc[mf][nf][1] + b1);
            float2 o1 = make_float2(acc[mf][nf][2] + b0, acc[mf][nf][3] + b1);
            *(float2*)(C + (size_t)r * 256 + cc) = o0;
            *(float2*)(C + (size_t)(r + 8) * 256 + cc) = o1;
        }
    }
}

// ---------------------------------------------------------------------------
// Attention (unchanged): out(64x32) = A(64x80) @ [local 64 | sel 16](80x32)
// ---------------------------------------------------------------------------
__global__ __launch_bounds__(128) void attn_kernel(const float* __restrict__ aw,
                                                   const int*   __restrict__ idx,
                                                   const float* __restrict__ wsel)
{
    __shared__ float sA[64][81];
    __shared__ float sX[80][32];

    const int t   = threadIdx.x;
    const int bid = blockIdx.x;
    const int blk = bid & 255;
    const int b   = (bid >> 8) & 7;
    const int h   = bid >> 11;
    const int bh  = blk >> 4;
    const int bw  = blk & 15;

    const float* Ab = aw + (size_t)bid * 5120;
#pragma unroll
    for (int i = 0; i < 10; i++) {
        const int v  = i * 128 + t;
        const int q  = v / 20;
        const int kq = (v % 20) << 2;
        const float4 a4 = *(const float4*)(Ab + q * 80 + kq);
        sA[q][kq + 0] = a4.x;
        sA[q][kq + 1] = a4.y;
        sA[q][kq + 2] = a4.z;
        sA[q][kq + 3] = a4.w;
    }

    const size_t xbase = (size_t)b * NTOK * 256 + h * 32;

#pragma unroll
    for (int i = 0; i < 4; i++) {
        const int v  = i * 128 + t;
        const int p  = v >> 3;
        const int dq = (v & 7) << 2;
        const int r  = p >> 3, c = p & 7;
        const int sp = (bh * 8 + r) * 128 + bw * 8 + c;
        *(float4*)&sX[p][dq] =
            *(const float4*)(g_xp + xbase + (size_t)sp * 256 + dq);
    }
    {
        const int j    = t >> 3;
        const int dq   = (t & 7) << 2;
        const int base = (b * 256 + blk) * 16 + j;
        const int tok  = idx[base];
        const float wv = wsel[base];
        const float4 v4 = *(const float4*)(g_xp + xbase + (size_t)tok * 256 + dq);
        sX[64 + j][dq + 0] = v4.x * wv;
        sX[64 + j][dq + 1] = v4.y * wv;
        sX[64 + j][dq + 2] = v4.z * wv;
        sX[64 + j][dq + 3] = v4.w * wv;
    }
    __syncthreads();

    const int qg = t >> 3;
    const int dg = t & 7;
    float acc[4][4];
#pragma unroll
    for (int i = 0; i < 4; i++)
#pragma unroll
        for (int j = 0; j < 4; j++) acc[i][j] = 0.f;

#pragma unroll 4
    for (int k = 0; k < 80; k++) {
        const float4 x4 = *(const float4*)&sX[k][dg << 2];
        const float xv[4] = {x4.x, x4.y, x4.z, x4.w};
#pragma unroll
        for (int i = 0; i < 4; i++) {
            const float a = sA[qg * 4 + i][k];
#pragma unroll
            for (int j = 0; j < 4; j++)
                acc[i][j] = fmaf(a, xv[j], acc[i][j]);
        }
    }

#pragma unroll
    for (int i = 0; i < 4; i++) {
        const int q  = qg * 4 + i;
        const int r  = q >> 3, c = q & 7;
        const int sp = (bh * 8 + r) * 128 + bw * 8 + c;
        const float4 o = make_float4(acc[i][0], acc[i][1], acc[i][2], acc[i][3]);
        *(float4*)(g_y + xbase + (size_t)sp * 256 + (dg << 2)) = o;
    }
}

// ===========================================================================
extern "C" void kernel_launch(void* const* d_in, const int* in_sizes, int n_in,
                              void* d_out, int out_size)
{
    const float* x    = (const float*)d_in[0];
    const float* aw   = (const float*)d_in[1];
    const int*   idx  = (const int*)d_in[2];
    const float* wsel = (const float*)d_in[3];
    const float* Win  = (const float*)d_in[4];
    const float* bin  = (const float*)d_in[5];
    const float* Wout = (const float*)d_in[6];
    const float* bout = (const float*)d_in[7];
    float* out = (float*)d_out;

    float *xp_ptr, *y_ptr;
    __nv_bfloat16 *wth1, *wtl1, *wth2, *wtl2;
    cudaGetSymbolAddress((void**)&xp_ptr, g_xp);
    cudaGetSymbolAddress((void**)&y_ptr, g_y);
    cudaGetSymbolAddress((void**)&wth1, g_wth1);
    cudaGetSymbolAddress((void**)&wtl1, g_wtl1);
    cudaGetSymbolAddress((void**)&wth2, g_wth2);
    cudaGetSymbolAddress((void**)&wtl2, g_wtl2);

    cudaFuncSetAttribute(gemm_bf16x3,
                         cudaFuncAttributeMaxDynamicSharedMemorySize, GEMM_SMEM);

    transpose_split<<<64, 256>>>(Win, wth1, wtl1);
    transpose_split<<<64, 256>>>(Wout, wth2, wtl2);

    gemm_bf16x3<<<dim3(2, 1024), 256, GEMM_SMEM>>>(x, wth1, wtl1, bin, xp_ptr);
    attn_kernel<<<16384, 128>>>(aw, idx, wsel);
    gemm_bf16x3<<<dim3(2, 1024), 256, GEMM_SMEM>>>(y_ptr, wth2, wtl2, bout, out);
}

// round 5
// speedup vs baseline: 2.4378x; 1.4336x over previous
#include <cuda_runtime.h>
#include <cstdint>

#define NTOK 16384

// Scratch (allocation-free rule: __device__ globals)
__device__ float g_xp[33554432];   // x @ W_in
__device__ float g_y[33554432];    // attention output
__device__ float g_wt1[65536];     // W_in^T  [n][k], tf32-rounded fp32
__device__ float g_wt2[65536];     // W_out^T [n][k], tf32-rounded fp32

// ---------------------------------------------------------------------------
__device__ __forceinline__ uint32_t smem_u32(const void* p) {
    uint32_t a;
    asm("{ .reg .u64 t; cvta.to.shared.u64 t, %1; cvt.u32.u64 %0, t; }"
        : "=r"(a) : "l"(p));
    return a;
}
__device__ __forceinline__ float tf32r(float x) {
    uint32_t r;
    asm("cvt.rna.tf32.f32 %0, %1;" : "=r"(r) : "f"(x));
    return __uint_as_float(r);
}
__device__ __forceinline__ void mma_tf32(float* d, const uint32_t* a,
                                         const uint32_t* b) {
    asm volatile(
        "mma.sync.aligned.m16n8k8.row.col.f32.tf32.tf32.f32 "
        "{%0,%1,%2,%3}, {%4,%5,%6,%7}, {%8,%9}, {%0,%1,%2,%3};"
        : "+f"(d[0]), "+f"(d[1]), "+f"(d[2]), "+f"(d[3])
        : "r"(a[0]), "r"(a[1]), "r"(a[2]), "r"(a[3]), "r"(b[0]), "r"(b[1]));
}
#define CP_ASYNC16(dst, src) \
    asm volatile("cp.async.ca.shared.global [%0], [%1], 16;" \
                 :: "r"(dst), "l"(src))
#define CP_COMMIT() asm volatile("cp.async.commit_group;")
#define CP_WAIT0()  asm volatile("cp.async.wait_group 0;")

// ---------------------------------------------------------------------------
// Transpose + tf32 RN-round: Wt[n][k] = round_tf32(W[k][n]), 256x256
// ---------------------------------------------------------------------------
__global__ void transpose_tf32(const float* __restrict__ W, float* __restrict__ Wt)
{
    __shared__ float tile[32][33];
    const int bx = (blockIdx.x & 7) << 5;
    const int by = (blockIdx.x >> 3) << 5;
    const int tx = threadIdx.x & 31;
    const int ty = threadIdx.x >> 5;
#pragma unroll
    for (int i = 0; i < 32; i += 8)
        tile[ty + i][tx] = W[(by + ty + i) * 256 + bx + tx];
    __syncthreads();
#pragma unroll
    for (int i = 0; i < 32; i += 8)
        Wt[(bx + ty + i) * 256 + by + tx] = tf32r(tile[tx][ty + i]);
}

// ---------------------------------------------------------------------------
// Single-pass TF32 GEMM: C[M x 256] = A @ Bt^T + bias
//   Bt [N][K] K-major, tf32-pre-rounded. CTA 128x128, BK=32, 256 thr,
//   8 warps (2M x 4N), warp tile 64x32. A: reg-prefetch + RN round.
//   B: cp.async. Frags via scalar LDS from stride-36 smem (conflict-free).
// ---------------------------------------------------------------------------
#define AST 36
#define ABUF_B (128 * AST * 4)            // 18432
#define BUFB   (2 * ABUF_B)               // 36864 (A + B)
#define GEMM_SMEM (2 * BUFB)              // 73728

__global__ __launch_bounds__(256) void gemm_tf32(const float* __restrict__ A,
                                                 const float* __restrict__ Bt,
                                                 const float* __restrict__ bias,
                                                 float* __restrict__ C)
{
    extern __shared__ char sm[];
    const uint32_t smb = smem_u32(sm);
    const int t    = threadIdx.x;
    const int lane = t & 31;
    const int warp = t >> 5;
    const int wm0  = (warp >> 2) * 64;
    const int wn0  = (warp & 3) * 32;
    const int row0 = blockIdx.y << 7;
    const int col0 = blockIdx.x << 7;
    const int g    = lane >> 2;
    const int tg   = lane & 3;

    // staging map: per iter i, row = i*32 + lr, k-offset lk (4 floats)
    const int lr = t >> 3;          // 0..31
    const int lk = (t & 7) << 2;    // 0,4,...,28

    float acc[4][4][4];
#pragma unroll
    for (int i = 0; i < 4; i++)
#pragma unroll
        for (int j = 0; j < 4; j++)
#pragma unroll
            for (int k = 0; k < 4; k++) acc[i][j][k] = 0.f;

    float4 pa[4];

#define B_ASYNC(k0, bufoff)                                                    \
    do {                                                                       \
        _Pragma("unroll")                                                      \
        for (int i = 0; i < 4; i++) {                                          \
            const int n = i * 32 + lr;                                         \
            CP_ASYNC16(smb + (bufoff) + ABUF_B + (uint32_t)(n * AST + lk) * 4, \
                       Bt + (size_t)(col0 + n) * 256 + (k0) + lk);             \
        }                                                                      \
        CP_COMMIT();                                                           \
    } while (0)

#define A_LOAD(k0)                                                             \
    do {                                                                       \
        _Pragma("unroll")                                                      \
        for (int i = 0; i < 4; i++)                                            \
            pa[i] = *(const float4*)(A + (size_t)(row0 + i * 32 + lr) * 256 +  \
                                     (k0) + lk);                               \
    } while (0)

#define A_STORE(bufoff)                                                        \
    do {                                                                       \
        _Pragma("unroll")                                                      \
        for (int i = 0; i < 4; i++) {                                          \
            float4 v;                                                          \
            v.x = tf32r(pa[i].x); v.y = tf32r(pa[i].y);                        \
            v.z = tf32r(pa[i].z); v.w = tf32r(pa[i].w);                        \
            *(float4*)(sm + (bufoff) + (uint32_t)((i * 32 + lr) * AST + lk) * 4) = v; \
        }                                                                      \
    } while (0)

    // prologue: stage chunk 0
    A_LOAD(0);
    B_ASYNC(0, 0);
    A_STORE(0);
    CP_WAIT0();
    __syncthreads();

    for (int c = 0; c < 8; c++) {
        const uint32_t cur = (uint32_t)(c & 1) * BUFB;
        const uint32_t nxt = BUFB - cur;
        if (c < 7) {
            B_ASYNC((c + 1) * 32, nxt);
            A_LOAD((c + 1) * 32);
        }

        const float* As = (const float*)(sm + cur);
        const float* Bs = (const float*)(sm + cur + ABUF_B);

#pragma unroll
        for (int ks = 0; ks < 4; ks++) {
            const int kk = ks * 8;
            uint32_t af[4][4], bf[4][2];
#pragma unroll
            for (int mf = 0; mf < 4; mf++) {
                const int r = wm0 + mf * 16 + g;
                af[mf][0] = __float_as_uint(As[r * AST + kk + tg]);
                af[mf][1] = __float_as_uint(As[(r + 8) * AST + kk + tg]);
                af[mf][2] = __float_as_uint(As[r * AST + kk + tg + 4]);
                af[mf][3] = __float_as_uint(As[(r + 8) * AST + kk + tg + 4]);
            }
#pragma unroll
            for (int nf = 0; nf < 4; nf++) {
                const int n = wn0 + nf * 8 + g;
                bf[nf][0] = __float_as_uint(Bs[n * AST + kk + tg]);
                bf[nf][1] = __float_as_uint(Bs[n * AST + kk + tg + 4]);
            }
#pragma unroll
            for (int mf = 0; mf < 4; mf++)
#pragma unroll
                for (int nf = 0; nf < 4; nf++)
                    mma_tf32(acc[mf][nf], af[mf], bf[nf]);
        }

        if (c < 7) {
            A_STORE(nxt);
            CP_WAIT0();
        }
        __syncthreads();
    }

    // Epilogue: +bias, direct float2 stores (m16n8 C frag layout)
#pragma unroll
    for (int nf = 0; nf < 4; nf++) {
        const int cc = col0 + wn0 + nf * 8 + tg * 2;
        const float b0 = bias[cc], b1 = bias[cc + 1];
#pragma unroll
        for (int mf = 0; mf < 4; mf++) {
            const int r = row0 + wm0 + mf * 16 + g;
            float2 o0 = make_float2(acc[mf][nf][0] + b0, acc[mf][nf][1] + b1);
            float2 o1 = make_float2(acc[mf][nf][2] + b0, acc[mf][nf][3] + b1);
            *(float2*)(C + (size_t)r * 256 + cc) = o0;
            *(float2*)(C + (size_t)(r + 8) * 256 + cc) = o1;
        }
    }
}

// ---------------------------------------------------------------------------
// Attention (vectorized fp32): out(64x32) = A(64x80) @ [local 64|sel 16](80x32)
// Inner loop: per 4k -> 8 LDS.128, 64 FMA per thread.
// ---------------------------------------------------------------------------
__global__ __launch_bounds__(128) void attn_kernel(const float* __restrict__ aw,
                                                   const int*   __restrict__ idx,
                                                   const float* __restrict__ wsel)
{
    __shared__ float sA[64 * 84];   // stride 84 floats (21 float4) per q-row
    __shared__ float sX[80 * 32];   // row k: 32 floats (8 float4)

    const int t   = threadIdx.x;
    const int bid = blockIdx.x;
    const int blk = bid & 255;
    const int b   = (bid >> 8) & 7;
    const int h   = bid >> 11;
    const int bh  = blk >> 4;
    const int bw  = blk & 15;

    float4* sA4 = (float4*)sA;
    float4* sX4 = (float4*)sX;

    // Load A: 64x80 = 1280 float4, 10 per thread
    const float* Ab = aw + (size_t)bid * 5120;
#pragma unroll
    for (int i = 0; i < 10; i++) {
        const int v = i * 128 + t;
        const int q = v / 20;
        const int m = v % 20;
        sA4[q * 21 + m] = *(const float4*)(Ab + q * 80 + m * 4);
    }

    const size_t xbase = (size_t)b * NTOK * 256 + h * 32;

    // Local tokens: 64 x 32ch = 512 float4, 4/thread
#pragma unroll
    for (int i = 0; i < 4; i++) {
        const int v  = i * 128 + t;
        const int p  = v >> 3;
        const int dq = v & 7;
        const int r  = p >> 3, c = p & 7;
        const int sp = (bh * 8 + r) * 128 + bw * 8 + c;
        sX4[p * 8 + dq] = *(const float4*)(g_xp + xbase + (size_t)sp * 256 + dq * 4);
    }
    // Selected tokens: 16 x 32ch = 128 float4, 1/thread
    {
        const int j    = t >> 3;
        const int dq   = t & 7;
        const int base = (b * 256 + blk) * 16 + j;
        const int tok  = idx[base];
        const float w  = wsel[base];
        float4 v4 = *(const float4*)(g_xp + xbase + (size_t)tok * 256 + dq * 4);
        v4.x *= w; v4.y *= w; v4.z *= w; v4.w *= w;
        sX4[(64 + j) * 8 + dq] = v4;
    }
    __syncthreads();

    const int qg = t >> 3;   // 0..15: rows qg*4..+3
    const int dg = t & 7;    // 0..7 : cols dg*4..+3
    float acc[4][4];
#pragma unroll
    for (int i = 0; i < 4; i++)
#pragma unroll
        for (int j = 0; j < 4; j++) acc[i][j] = 0.f;

#pragma unroll 5
    for (int k4 = 0; k4 < 20; k4++) {
        const float4 x0 = sX4[(k4 * 4 + 0) * 8 + dg];
        const float4 x1 = sX4[(k4 * 4 + 1) * 8 + dg];
        const float4 x2 = sX4[(k4 * 4 + 2) * 8 + dg];
        const float4 x3 = sX4[(k4 * 4 + 3) * 8 + dg];
#pragma unroll
        for (int i = 0; i < 4; i++) {
            const float4 a4 = sA4[(qg * 4 + i) * 21 + k4];
            acc[i][0] = fmaf(a4.x, x0.x, acc[i][0]);
            acc[i][1] = fmaf(a4.x, x0.y, acc[i][1]);
            acc[i][2] = fmaf(a4.x, x0.z, acc[i][2]);
            acc[i][3] = fmaf(a4.x, x0.w, acc[i][3]);
            acc[i][0] = fmaf(a4.y, x1.x, acc[i][0]);
            acc[i][1] = fmaf(a4.y, x1.y, acc[i][1]);
            acc[i][2] = fmaf(a4.y, x1.z, acc[i][2]);
            acc[i][3] = fmaf(a4.y, x1.w, acc[i][3]);
            acc[i][0] = fmaf(a4.z, x2.x, acc[i][0]);
            acc[i][1] = fmaf(a4.z, x2.y, acc[i][1]);
            acc[i][2] = fmaf(a4.z, x2.z, acc[i][2]);
            acc[i][3] = fmaf(a4.z, x2.w, acc[i][3]);
            acc[i][0] = fmaf(a4.w, x3.x, acc[i][0]);
            acc[i][1] = fmaf(a4.w, x3.y, acc[i][1]);
            acc[i][2] = fmaf(a4.w, x3.z, acc[i][2]);
            acc[i][3] = fmaf(a4.w, x3.w, acc[i][3]);
        }
    }

    // Scatter to token-major y
#pragma unroll
    for (int i = 0; i < 4; i++) {
        const int q  = qg * 4 + i;
        const int r  = q >> 3, c = q & 7;
        const int sp = (bh * 8 + r) * 128 + bw * 8 + c;
        const float4 o = make_float4(acc[i][0], acc[i][1], acc[i][2], acc[i][3]);
        *(float4*)(g_y + xbase + (size_t)sp * 256 + dg * 4) = o;
    }
}

// ===========================================================================
extern "C" void kernel_launch(void* const* d_in, const int* in_sizes, int n_in,
                              void* d_out, int out_size)
{
    const float* x    = (const float*)d_in[0];
    const float* aw   = (const float*)d_in[1];
    const int*   idx  = (const int*)d_in[2];
    const float* wsel = (const float*)d_in[3];
    const float* Win  = (const float*)d_in[4];
    const float* bin  = (const float*)d_in[5];
    const float* Wout = (const float*)d_in[6];
    const float* bout = (const float*)d_in[7];
    float* out = (float*)d_out;

    float *xp_ptr, *y_ptr, *wt1, *wt2;
    cudaGetSymbolAddress((void**)&xp_ptr, g_xp);
    cudaGetSymbolAddress((void**)&y_ptr, g_y);
    cudaGetSymbolAddress((void**)&wt1, g_wt1);
    cudaGetSymbolAddress((void**)&wt2, g_wt2);

    cudaFuncSetAttribute(gemm_tf32,
                         cudaFuncAttributeMaxDynamicSharedMemorySize, GEMM_SMEM);

    transpose_tf32<<<64, 256>>>(Win, wt1);
    transpose_tf32<<<64, 256>>>(Wout, wt2);

    gemm_tf32<<<dim3(2, 1024), 256, GEMM_SMEM>>>(x, wt1, bin, xp_ptr);
    attn_kernel<<<16384, 128>>>(aw, idx, wsel);
    gemm_tf32<<<dim3(2, 1024), 256, GEMM_SMEM>>>(y_ptr, wt2, bout, out);
}

// round 6
// speedup vs baseline: 2.5718x; 1.0550x over previous
#include <cuda_runtime.h>
#include <cstdint>

#define NTOK 16384

// Scratch (allocation-free rule: __device__ globals)
__device__ float g_xp[33554432];   // x @ W_in
__device__ float g_y[33554432];    // attention output
__device__ float g_wt1[65536];     // W_in^T  [n][k], tf32-rounded fp32
__device__ float g_wt2[65536];     // W_out^T [n][k], tf32-rounded fp32

// ---------------------------------------------------------------------------
__device__ __forceinline__ uint32_t smem_u32(const void* p) {
    uint32_t a;
    asm("{ .reg .u64 t; cvta.to.shared.u64 t, %1; cvt.u32.u64 %0, t; }"
        : "=r"(a) : "l"(p));
    return a;
}
__device__ __forceinline__ float tf32r(float x) {
    uint32_t r;
    asm("cvt.rna.tf32.f32 %0, %1;" : "=r"(r) : "f"(x));
    return __uint_as_float(r);
}
__device__ __forceinline__ void mma_tf32(float* d, const uint32_t* a,
                                         const uint32_t* b) {
    asm volatile(
        "mma.sync.aligned.m16n8k8.row.col.f32.tf32.tf32.f32 "
        "{%0,%1,%2,%3}, {%4,%5,%6,%7}, {%8,%9}, {%0,%1,%2,%3};"
        : "+f"(d[0]), "+f"(d[1]), "+f"(d[2]), "+f"(d[3])
        : "r"(a[0]), "r"(a[1]), "r"(a[2]), "r"(a[3]), "r"(b[0]), "r"(b[1]));
}
#define CP_ASYNC16(dst, src) \
    asm volatile("cp.async.ca.shared.global [%0], [%1], 16;" \
                 :: "r"(dst), "l"(src))
#define CP_COMMIT() asm volatile("cp.async.commit_group;")
#define CP_WAIT0()  asm volatile("cp.async.wait_group 0;")

// ---------------------------------------------------------------------------
// Transpose + tf32 RN-round: Wt[n][k] = round_tf32(W[k][n]), 256x256
// ---------------------------------------------------------------------------
__global__ void transpose_tf32(const float* __restrict__ W, float* __restrict__ Wt)
{
    __shared__ float tile[32][33];
    const int bx = (blockIdx.x & 7) << 5;
    const int by = (blockIdx.x >> 3) << 5;
    const int tx = threadIdx.x & 31;
    const int ty = threadIdx.x >> 5;
#pragma unroll
    for (int i = 0; i < 32; i += 8)
        tile[ty + i][tx] = W[(by + ty + i) * 256 + bx + tx];
    __syncthreads();
#pragma unroll
    for (int i = 0; i < 32; i += 8)
        Wt[(bx + ty + i) * 256 + by + tx] = tf32r(tile[tx][ty + i]);
}

// ---------------------------------------------------------------------------
// Single-pass TF32 GEMM: C[M x 256] = A @ Bt^T + bias  (unchanged from R5)
// ---------------------------------------------------------------------------
#define AST 36
#define ABUF_B (128 * AST * 4)            // 18432
#define BUFB   (2 * ABUF_B)               // 36864 (A + B)
#define GEMM_SMEM (2 * BUFB)              // 73728

__global__ __launch_bounds__(256) void gemm_tf32(const float* __restrict__ A,
                                                 const float* __restrict__ Bt,
                                                 const float* __restrict__ bias,
                                                 float* __restrict__ C)
{
    extern __shared__ char sm[];
    const uint32_t smb = smem_u32(sm);
    const int t    = threadIdx.x;
    const int lane = t & 31;
    const int warp = t >> 5;
    const int wm0  = (warp >> 2) * 64;
    const int wn0  = (warp & 3) * 32;
    const int row0 = blockIdx.y << 7;
    const int col0 = blockIdx.x << 7;
    const int g    = lane >> 2;
    const int tg   = lane & 3;

    const int lr = t >> 3;          // 0..31
    const int lk = (t & 7) << 2;    // 0,4,...,28

    float acc[4][4][4];
#pragma unroll
    for (int i = 0; i < 4; i++)
#pragma unroll
        for (int j = 0; j < 4; j++)
#pragma unroll
            for (int k = 0; k < 4; k++) acc[i][j][k] = 0.f;

    float4 pa[4];

#define B_ASYNC(k0, bufoff)                                                    \
    do {                                                                       \
        _Pragma("unroll")                                                      \
        for (int i = 0; i < 4; i++) {                                          \
            const int n = i * 32 + lr;                                         \
            CP_ASYNC16(smb + (bufoff) + ABUF_B + (uint32_t)(n * AST + lk) * 4, \
                       Bt + (size_t)(col0 + n) * 256 + (k0) + lk);             \
        }                                                                      \
        CP_COMMIT();                                                           \
    } while (0)

#define A_LOAD(k0)                                                             \
    do {                                                                       \
        _Pragma("unroll")                                                      \
        for (int i = 0; i < 4; i++)                                            \
            pa[i] = *(const float4*)(A + (size_t)(row0 + i * 32 + lr) * 256 +  \
                                     (k0) + lk);                               \
    } while (0)

#define A_STORE(bufoff)                                                        \
    do {                                                                       \
        _Pragma("unroll")                                                      \
        for (int i = 0; i < 4; i++) {                                          \
            float4 v;                                                          \
            v.x = tf32r(pa[i].x); v.y = tf32r(pa[i].y);                        \
            v.z = tf32r(pa[i].z); v.w = tf32r(pa[i].w);                        \
            *(float4*)(sm + (bufoff) + (uint32_t)((i * 32 + lr) * AST + lk) * 4) = v; \
        }                                                                      \
    } while (0)

    A_LOAD(0);
    B_ASYNC(0, 0);
    A_STORE(0);
    CP_WAIT0();
    __syncthreads();

    for (int c = 0; c < 8; c++) {
        const uint32_t cur = (uint32_t)(c & 1) * BUFB;
        const uint32_t nxt = BUFB - cur;
        if (c < 7) {
            B_ASYNC((c + 1) * 32, nxt);
            A_LOAD((c + 1) * 32);
        }

        const float* As = (const float*)(sm + cur);
        const float* Bs = (const float*)(sm + cur + ABUF_B);

#pragma unroll
        for (int ks = 0; ks < 4; ks++) {
            const int kk = ks * 8;
            uint32_t af[4][4], bf[4][2];
#pragma unroll
            for (int mf = 0; mf < 4; mf++) {
                const int r = wm0 + mf * 16 + g;
                af[mf][0] = __float_as_uint(As[r * AST + kk + tg]);
                af[mf][1] = __float_as_uint(As[(r + 8) * AST + kk + tg]);
                af[mf][2] = __float_as_uint(As[r * AST + kk + tg + 4]);
                af[mf][3] = __float_as_uint(As[(r + 8) * AST + kk + tg + 4]);
            }
#pragma unroll
            for (int nf = 0; nf < 4; nf++) {
                const int n = wn0 + nf * 8 + g;
                bf[nf][0] = __float_as_uint(Bs[n * AST + kk + tg]);
                bf[nf][1] = __float_as_uint(Bs[n * AST + kk + tg + 4]);
            }
#pragma unroll
            for (int mf = 0; mf < 4; mf++)
#pragma unroll
                for (int nf = 0; nf < 4; nf++)
                    mma_tf32(acc[mf][nf], af[mf], bf[nf]);
        }

        if (c < 7) {
            A_STORE(nxt);
            CP_WAIT0();
        }
        __syncthreads();
    }

#pragma unroll
    for (int nf = 0; nf < 4; nf++) {
        const int cc = col0 + wn0 + nf * 8 + tg * 2;
        const float b0 = bias[cc], b1 = bias[cc + 1];
#pragma unroll
        for (int mf = 0; mf < 4; mf++) {
            const int r = row0 + wm0 + mf * 16 + g;
            float2 o0 = make_float2(acc[mf][nf][0] + b0, acc[mf][nf][1] + b1);
            float2 o1 = make_float2(acc[mf][nf][2] + b0, acc[mf][nf][3] + b1);
            *(float2*)(C + (size_t)r * 256 + cc) = o0;
            *(float2*)(C + (size_t)(r + 8) * 256 + cc) = o1;
        }
    }
}

// ---------------------------------------------------------------------------
// TF32-MMA attention: per (h,b,blk): D(64x32) = A(64x80) @ X(80x32).
//   A staged [q][k] stride 84 (a-frag LDS conflict-free: bank=20g+tg+C).
//   X staged TRANSPOSED [ch][tok] stride 84 (b-frag conflict-free, same math).
//   4 warps split M (16 rows each); 40 MMA/warp; 128 thr/CTA; grid 16384.
// ---------------------------------------------------------------------------
__global__ __launch_bounds__(128) void attn_mma(const float* __restrict__ aw,
                                                const int*   __restrict__ idx,
                                                const float* __restrict__ wsel)
{
    __shared__ float sA[64 * 84];    // A[q][k], 80+4 pad
    __shared__ float sXT[32 * 84];   // X^T[ch][tok], 80+4 pad

    const int t    = threadIdx.x;
    const int bid  = blockIdx.x;
    const int blk  = bid & 255;
    const int b    = (bid >> 8) & 7;
    const int h    = bid >> 11;
    const int bh   = blk >> 4;
    const int bw   = blk & 15;
    const int lane = t & 31;
    const int warp = t >> 5;
    const int g    = lane >> 2;
    const int tg   = lane & 3;

    // ---- stage A (64x80 contiguous): 1280 float4, 10/thread, tf32-rounded
    const float* Ab = aw + (size_t)bid * 5120;
#pragma unroll
    for (int i = 0; i < 10; i++) {
        const int v = i * 128 + t;
        const int q = v / 20;
        const int m = v % 20;
        const float4 a = *(const float4*)(Ab + q * 80 + m * 4);
        float* d = sA + q * 84 + m * 4;
        d[0] = tf32r(a.x); d[1] = tf32r(a.y);
        d[2] = tf32r(a.z); d[3] = tf32r(a.w);
    }

    const size_t xbase = (size_t)b * NTOK * 256 + h * 32;

    // ---- stage X^T: local 64 tokens (512 float4, 4/thread), transposed store
#pragma unroll
    for (int i = 0; i < 4; i++) {
        const int v  = i * 128 + t;
        const int p  = v >> 3;          // token 0..63
        const int dq = v & 7;           // channel quad
        const int r  = p >> 3, c = p & 7;
        const int sp = (bh * 8 + r) * 128 + bw * 8 + c;
        const float4 x = *(const float4*)(g_xp + xbase + (size_t)sp * 256 + dq * 4);
        sXT[(dq * 4 + 0) * 84 + p] = tf32r(x.x);
        sXT[(dq * 4 + 1) * 84 + p] = tf32r(x.y);
        sXT[(dq * 4 + 2) * 84 + p] = tf32r(x.z);
        sXT[(dq * 4 + 3) * 84 + p] = tf32r(x.w);
    }
    // ---- stage X^T: selected 16 tokens (128 float4, 1/thread), weighted
    {
        const int j    = t >> 3;
        const int dq   = t & 7;
        const int base = (b * 256 + blk) * 16 + j;
        const int tok  = idx[base];
        const float w  = wsel[base];
        const float4 x = *(const float4*)(g_xp + xbase + (size_t)tok * 256 + dq * 4);
        sXT[(dq * 4 + 0) * 84 + 64 + j] = tf32r(x.x * w);
        sXT[(dq * 4 + 1) * 84 + 64 + j] = tf32r(x.y * w);
        sXT[(dq * 4 + 2) * 84 + 64 + j] = tf32r(x.z * w);
        sXT[(dq * 4 + 3) * 84 + 64 + j] = tf32r(x.w * w);
    }
    __syncthreads();

    // ---- MMA: warp handles rows [m0, m0+16); 10 k-steps x 4 n-tiles
    const int m0 = warp << 4;
    float acc[4][4];
#pragma unroll
    for (int i = 0; i < 4; i++)
#pragma unroll
        for (int j = 0; j < 4; j++) acc[i][j] = 0.f;

#pragma unroll
    for (int ks = 0; ks < 10; ks++) {
        const int kk = ks * 8;
        uint32_t af[4];
        af[0] = __float_as_uint(sA[(m0 + g) * 84 + kk + tg]);
        af[1] = __float_as_uint(sA[(m0 + g + 8) * 84 + kk + tg]);
        af[2] = __float_as_uint(sA[(m0 + g) * 84 + kk + tg + 4]);
        af[3] = __float_as_uint(sA[(m0 + g + 8) * 84 + kk + tg + 4]);
#pragma unroll
        for (int nf = 0; nf < 4; nf++) {
            uint32_t bf[2];
            bf[0] = __float_as_uint(sXT[(nf * 8 + g) * 84 + kk + tg]);
            bf[1] = __float_as_uint(sXT[(nf * 8 + g) * 84 + kk + tg + 4]);
            mma_tf32(acc[nf], af, bf);
        }
    }

    // ---- scatter D to token-major y (c-frag: rows g/g+8, cols 2tg/2tg+1)
#pragma unroll
    for (int nf = 0; nf < 4; nf++) {
#pragma unroll
        for (int half = 0; half < 2; half++) {
            const int q  = m0 + g + half * 8;
            const int r  = q >> 3, c = q & 7;
            const int sp = (bh * 8 + r) * 128 + bw * 8 + c;
            const float2 o = make_float2(acc[nf][half * 2 + 0],
                                         acc[nf][half * 2 + 1]);
            *(float2*)(g_y + xbase + (size_t)sp * 256 + nf * 8 + tg * 2) = o;
        }
    }
}

// ===========================================================================
extern "C" void kernel_launch(void* const* d_in, const int* in_sizes, int n_in,
                              void* d_out, int out_size)
{
    const float* x    = (const float*)d_in[0];
    const float* aw   = (const float*)d_in[1];
    const int*   idx  = (const int*)d_in[2];
    const float* wsel = (const float*)d_in[3];
    const float* Win  = (const float*)d_in[4];
    const float* bin  = (const float*)d_in[5];
    const float* Wout = (const float*)d_in[6];
    const float* bout = (const float*)d_in[7];
    float* out = (float*)d_out;

    float *xp_ptr, *y_ptr, *wt1, *wt2;
    cudaGetSymbolAddress((void**)&xp_ptr, g_xp);
    cudaGetSymbolAddress((void**)&y_ptr, g_y);
    cudaGetSymbolAddress((void**)&wt1, g_wt1);
    cudaGetSymbolAddress((void**)&wt2, g_wt2);

    cudaFuncSetAttribute(gemm_tf32,
                         cudaFuncAttributeMaxDynamicSharedMemorySize, GEMM_SMEM);

    transpose_tf32<<<64, 256>>>(Win, wt1);
    transpose_tf32<<<64, 256>>>(Wout, wt2);

    gemm_tf32<<<dim3(2, 1024), 256, GEMM_SMEM>>>(x, wt1, bin, xp_ptr);
    attn_mma<<<16384, 128>>>(aw, idx, wsel);
    gemm_tf32<<<dim3(2, 1024), 256, GEMM_SMEM>>>(y_ptr, wt2, bout, out);
}